// round 9
// baseline (speedup 1.0000x reference)
#include <cuda_runtime.h>
#include <cuda_bf16.h>
#include <cstdint>

#define Bb 64
#define Nn 64
#define KDIM 512
#define NOUT 480           // NT*SEM = 30*16
#define ROWS 4096
#define NSPAN 2016
#define NP1 65

// Scratch — __device__ globals (no allocation allowed)
__device__ float g_h[ROWS * NOUT];            // 7.86 MB
__device__ float g_prefix[Bb * NP1 * NOUT];   // 7.99 MB

// ---------------------------------------------------------------------------
// Kernel 1: fused gather + GEMM  h = emb[x] @ w_out^T + b_out
// Tensor-core bf16 hi/lo split (3 mma per pair), fp32 accumulate.
// BM=128, BN=48, BK=32, 256 threads (8 warps as 4m x 2n), warp tile 32x24.
// Grid 32x10 = 320 blocks -> 2 blocks/SM co-resident.
// ---------------------------------------------------------------------------
#define BM 128
#define BN 48
#define BK 32
#define APITCH 40          // bf16 elems per smem row (conflict-free banks)

__device__ __forceinline__ void split2(float x, float y, unsigned& hi, unsigned& lo) {
    // hi = {bf16(y), bf16(x)} with x in low half
    asm("cvt.rn.bf16x2.f32 %0, %1, %2;" : "=r"(hi) : "f"(y), "f"(x));
    const float rx = x - __uint_as_float(hi << 16);
    const float ry = y - __uint_as_float(hi & 0xffff0000u);
    asm("cvt.rn.bf16x2.f32 %0, %1, %2;" : "=r"(lo) : "f"(ry), "f"(rx));
}

#define MMA_BF16(c, a, b0_, b1_)                                          \
    asm volatile(                                                         \
        "mma.sync.aligned.m16n8k16.row.col.f32.bf16.bf16.f32 "            \
        "{%0,%1,%2,%3}, {%4,%5,%6,%7}, {%8,%9}, {%0,%1,%2,%3};"           \
        : "+f"((c)[0]), "+f"((c)[1]), "+f"((c)[2]), "+f"((c)[3])          \
        : "r"((a)[0]), "r"((a)[1]), "r"((a)[2]), "r"((a)[3]),             \
          "r"(b0_), "r"(b1_))

__global__ __launch_bounds__(256, 2) void gemm_kernel(
    const int* __restrict__ x, const float* __restrict__ emb,
    const float* __restrict__ w, const float* __restrict__ bo)
{
    __shared__ __align__(16) __nv_bfloat16 sAhi[BM * APITCH];
    __shared__ __align__(16) __nv_bfloat16 sAlo[BM * APITCH];
    __shared__ __align__(16) __nv_bfloat16 sWhi[BN * APITCH];
    __shared__ __align__(16) __nv_bfloat16 sWlo[BN * APITCH];
    __shared__ int rowidx[BM];

    const int tid = threadIdx.x;
    const int m0 = blockIdx.x * BM;
    const int n0 = blockIdx.y * BN;

    if (tid < BM) rowidx[tid] = x[m0 + tid];
    __syncthreads();

    // ---- loader mappings ----
    // A tile: 128 rows x 32 k = 1024 float4; 4 per thread
    const float* aptr[4];
#pragma unroll
    for (int i = 0; i < 4; i++) {
        const int idx = tid + 256 * i;
        aptr[i] = emb + (size_t)rowidx[idx >> 3] * KDIM + (idx & 7) * 4;
    }
    // W tile: 48 rows x 32 k = 384 float4; 1.5 per thread (2nd for tid<128)
    const bool w2 = (tid < 128);
    const int widx1 = w2 ? (tid + 256) : tid;
    const float* wptr0 = w + (size_t)(n0 + (tid >> 3)) * KDIM + (tid & 7) * 4;
    const float* wptr1 = w + (size_t)(n0 + (widx1 >> 3)) * KDIM + (widx1 & 7) * 4;

    const int lane = tid & 31;
    const int grp = lane >> 2;
    const int qid = lane & 3;
    const int warpid = tid >> 5;
    const int wm = warpid & 3;   // m quadrant: rows wm*32
    const int wn = warpid >> 2;  // n half: cols wn*24

    const int aoff = (wm * 32 + grp) * APITCH + qid * 2;   // bf16 units
    const int boff = (wn * 24 + grp) * APITCH + qid * 2;

    float acc[2][3][4];
#pragma unroll
    for (int ma = 0; ma < 2; ma++)
#pragma unroll
        for (int j = 0; j < 3; j++)
#pragma unroll
            for (int c = 0; c < 4; c++) acc[ma][j][c] = 0.0f;

    for (int kt = 0; kt < KDIM / BK; kt++) {
        float4 va[4], vw0, vw1;
#pragma unroll
        for (int i = 0; i < 4; i++) va[i] = *(const float4*)(aptr[i] + kt * BK);
        vw0 = *(const float4*)(wptr0 + kt * BK);
        vw1 = *(const float4*)(wptr1 + kt * BK);

        __syncthreads();   // previous compute done before smem overwrite

#pragma unroll
        for (int i = 0; i < 4; i++) {
            const int idx = tid + 256 * i;
            const int off = (idx >> 3) * APITCH + (idx & 7) * 4;
            uint2 h, l;
            split2(va[i].x, va[i].y, h.x, l.x);
            split2(va[i].z, va[i].w, h.y, l.y);
            *(uint2*)(sAhi + off) = h;
            *(uint2*)(sAlo + off) = l;
        }
        {
            const int off = (tid >> 3) * APITCH + (tid & 7) * 4;
            uint2 h, l;
            split2(vw0.x, vw0.y, h.x, l.x);
            split2(vw0.z, vw0.w, h.y, l.y);
            *(uint2*)(sWhi + off) = h;
            *(uint2*)(sWlo + off) = l;
        }
        if (w2) {
            const int off = (widx1 >> 3) * APITCH + (widx1 & 7) * 4;
            uint2 h, l;
            split2(vw1.x, vw1.y, h.x, l.x);
            split2(vw1.z, vw1.w, h.y, l.y);
            *(uint2*)(sWhi + off) = h;
            *(uint2*)(sWlo + off) = l;
        }
        __syncthreads();

#pragma unroll
        for (int kb = 0; kb < BK; kb += 16) {
            unsigned ah[2][4], al[2][4];
#pragma unroll
            for (int ma = 0; ma < 2; ma++) {
                const int base = aoff + ma * 16 * APITCH + kb;
                ah[ma][0] = *(const unsigned*)(sAhi + base);
                ah[ma][1] = *(const unsigned*)(sAhi + base + 8 * APITCH);
                ah[ma][2] = *(const unsigned*)(sAhi + base + 8);
                ah[ma][3] = *(const unsigned*)(sAhi + base + 8 * APITCH + 8);
                al[ma][0] = *(const unsigned*)(sAlo + base);
                al[ma][1] = *(const unsigned*)(sAlo + base + 8 * APITCH);
                al[ma][2] = *(const unsigned*)(sAlo + base + 8);
                al[ma][3] = *(const unsigned*)(sAlo + base + 8 * APITCH + 8);
            }
#pragma unroll
            for (int j = 0; j < 3; j++) {
                const int bbase = boff + j * 8 * APITCH + kb;
                const unsigned bh0 = *(const unsigned*)(sWhi + bbase);
                const unsigned bh1 = *(const unsigned*)(sWhi + bbase + 8);
                const unsigned bl0 = *(const unsigned*)(sWlo + bbase);
                const unsigned bl1 = *(const unsigned*)(sWlo + bbase + 8);
#pragma unroll
                for (int ma = 0; ma < 2; ma++) {
                    MMA_BF16(acc[ma][j], ah[ma], bh0, bh1);
                    MMA_BF16(acc[ma][j], ah[ma], bl0, bl1);
                    MMA_BF16(acc[ma][j], al[ma], bh0, bh1);
                }
            }
        }
    }

    // Epilogue: add bias, store fp32 h
#pragma unroll
    for (int j = 0; j < 3; j++) {
        const int col = n0 + wn * 24 + j * 8 + qid * 2;
        const float2 bj = *(const float2*)(bo + col);
#pragma unroll
        for (int ma = 0; ma < 2; ma++) {
            const int row0 = m0 + wm * 32 + ma * 16 + grp;
            float2 v0, v1;
            v0.x = acc[ma][j][0] + bj.x;
            v0.y = acc[ma][j][1] + bj.y;
            v1.x = acc[ma][j][2] + bj.x;
            v1.y = acc[ma][j][3] + bj.y;
            *(float2*)(g_h + (size_t)row0 * NOUT + col) = v0;
            *(float2*)(g_h + (size_t)(row0 + 8) * NOUT + col) = v1;
        }
    }
}

// ---------------------------------------------------------------------------
// Kernel 2: masked cumsum over sequence -> prefix [B, N+1, 480]
// ---------------------------------------------------------------------------
__global__ __launch_bounds__(120) void prefix_kernel(const int* __restrict__ lengths)
{
    const int b = blockIdx.y;
    const int o = blockIdx.x * 120 + threadIdx.x;
    const int len = lengths[b];
    float acc = 0.0f;
    g_prefix[((size_t)b * NP1 + 0) * NOUT + o] = 0.0f;
#pragma unroll 8
    for (int n = 0; n < Nn; n++) {
        const float v = g_h[((size_t)b * Nn + n) * NOUT + o];
        if (n < len) acc += v;
        g_prefix[((size_t)b * NP1 + n + 1) * NOUT + o] = acc;
    }
}

// ---------------------------------------------------------------------------
// Kernel 3: span features + L2 norm, smem-tiled over 8x8 (l, r) tiles.
// ---------------------------------------------------------------------------
#define STH 256

__global__ __launch_bounds__(STH) void span_kernel(float* __restrict__ out)
{
    __shared__ float sL[8][NOUT];
    __shared__ float sR[8][NOUT];

    const int b = blockIdx.y;
    const int t = blockIdx.x;                 // 0..35, t = rt*(rt+1)/2 + lt
    int rt = 0;
    while ((rt + 1) * (rt + 2) / 2 <= t) rt++;
    const int lt = t - rt * (rt + 1) / 2;

    const int tid = threadIdx.x;
    const float* pb = g_prefix + (size_t)b * NP1 * NOUT;

    for (int i4 = tid; i4 < 16 * (NOUT / 4); i4 += STH) {
        const int row = i4 / (NOUT / 4);
        const int pos = i4 % (NOUT / 4);
        const int grow = (row < 8) ? (lt * 8 + row) : (rt * 8 + (row - 8) + 1);
        const float4 v = *(const float4*)(pb + (size_t)grow * NOUT + pos * 4);
        if (row < 8) *(float4*)&sL[row][pos * 4] = v;
        else         *(float4*)&sR[row - 8][pos * 4] = v;
    }
    __syncthreads();

    const int slot = tid / 60;        // 0..3 active, 4 = spare
    const int lane = tid % 60;
    const int base = (slot < 4) ? slot : 0;
    const bool diag = (lt == rt);

#pragma unroll 4
    for (int i = 0; i < 16; i++) {
        const int sp = base + 4 * i;          // 0..63
        const int li = sp & 7;
        const int ri = sp >> 3;

        const float4* Rp = (const float4*)&sR[ri][0];
        const float4* Lp = (const float4*)&sL[li][0];
        const float4 ra = Rp[lane],      la = Lp[lane];
        const float4 rb = Rp[60 + lane], lb = Lp[60 + lane];

        float4 da, db;
        da.x = ra.x - la.x; da.y = ra.y - la.y; da.z = ra.z - la.z; da.w = ra.w - la.w;
        db.x = rb.x - lb.x; db.y = rb.y - lb.y; db.z = rb.z - lb.z; db.w = rb.w - lb.w;

        float sqA = da.x * da.x;
        sqA = fmaf(da.y, da.y, sqA); sqA = fmaf(da.z, da.z, sqA); sqA = fmaf(da.w, da.w, sqA);
        float sqB = db.x * db.x;
        sqB = fmaf(db.y, db.y, sqB); sqB = fmaf(db.z, db.z, sqB); sqB = fmaf(db.w, db.w, sqB);

        sqA += __shfl_xor_sync(0xffffffffu, sqA, 1);
        sqA += __shfl_xor_sync(0xffffffffu, sqA, 2);
        sqB += __shfl_xor_sync(0xffffffffu, sqB, 1);
        sqB += __shfl_xor_sync(0xffffffffu, sqB, 2);

        const float invA = rsqrtf(sqA);
        const float invB = rsqrtf(sqB);

        if (slot < 4 && (!diag || li < ri)) {
            const int l = lt * 8 + li;
            const int r = rt * 8 + ri;
            const int k = r - l;
            const int s = (((k - 1) * (128 - k)) >> 1) + l;
            float* op = out + (size_t)(b * NSPAN + s) * NOUT;
            float4 oa, ob;
            oa.x = da.x * invA; oa.y = da.y * invA; oa.z = da.z * invA; oa.w = da.w * invA;
            ob.x = db.x * invB; ob.y = db.y * invB; ob.z = db.z * invB; ob.w = db.w * invB;
            *(float4*)(op + lane * 4) = oa;
            *(float4*)(op + 240 + lane * 4) = ob;
        }
    }
}

// ---------------------------------------------------------------------------
extern "C" void kernel_launch(void* const* d_in, const int* in_sizes, int n_in,
                              void* d_out, int out_size)
{
    const int*   x       = (const int*)d_in[0];
    const int*   lengths = (const int*)d_in[1];
    const float* emb     = (const float*)d_in[2];
    const float* w_out   = (const float*)d_in[3];
    const float* b_out   = (const float*)d_in[4];
    float* out = (float*)d_out;

    gemm_kernel<<<dim3(ROWS / BM, NOUT / BN), 256>>>(x, emb, w_out, b_out);
    prefix_kernel<<<dim3(4, Bb), 120>>>(lengths);
    span_kernel<<<dim3(36, Bb), STH>>>(out);
}

// round 13
// speedup vs baseline: 1.0535x; 1.0535x over previous
#include <cuda_runtime.h>
#include <cuda_bf16.h>
#include <cstdint>

#define Bb 64
#define Nn 64
#define KDIM 512
#define NOUT 480           // NT*SEM = 30*16
#define ROWS 4096
#define NSPAN 2016
#define NP1 65

// Scratch — __device__ globals (no allocation allowed)
__device__ float g_h[ROWS * NOUT];                 // 7.86 MB
__device__ float g_prefix[Bb * NP1 * NOUT];        // 7.99 MB
__device__ __nv_bfloat16 g_ahi[ROWS * KDIM];       // 4 MB
__device__ __nv_bfloat16 g_alo[ROWS * KDIM];       // 4 MB
__device__ __nv_bfloat16 g_whi[NOUT * KDIM];       // 0.5 MB
__device__ __nv_bfloat16 g_wlo[NOUT * KDIM];       // 0.5 MB

__device__ __forceinline__ void split2(float x, float y, unsigned& hi, unsigned& lo) {
    // hi = {bf16(y), bf16(x)} with x in low half
    asm("cvt.rn.bf16x2.f32 %0, %1, %2;" : "=r"(hi) : "f"(y), "f"(x));
    const float rx = x - __uint_as_float(hi << 16);
    const float ry = y - __uint_as_float(hi & 0xffff0000u);
    asm("cvt.rn.bf16x2.f32 %0, %1, %2;" : "=r"(lo) : "f"(ry), "f"(rx));
}

// ---------------------------------------------------------------------------
// Kernel 0: gather + hi/lo split of A (emb[x]) and W into bf16 buffers.
// Blocks 0..511: A (8 rows each). Blocks 512..571: W (8 rows each).
// ---------------------------------------------------------------------------
__global__ __launch_bounds__(256) void prep_kernel(
    const int* __restrict__ x, const float* __restrict__ emb,
    const float* __restrict__ w)
{
    const int blk = blockIdx.x;
    const int tid = threadIdx.x;
    const bool isA = (blk < 512);
    const int rbase = (isA ? blk : (blk - 512)) * 8;

#pragma unroll
    for (int i = 0; i < 4; i++) {
        const int idx = tid + i * 256;          // 1024 float4 per block
        const int r8 = idx >> 7;                // 0..7
        const int pos = idx & 127;              // float4 index in row
        const int row = rbase + r8;
        const float* src;
        __nv_bfloat16 *dh, *dl;
        if (isA) {
            src = emb + (size_t)x[row] * KDIM + pos * 4;
            dh = g_ahi + (size_t)row * KDIM + pos * 4;
            dl = g_alo + (size_t)row * KDIM + pos * 4;
        } else {
            src = w + (size_t)row * KDIM + pos * 4;
            dh = g_whi + (size_t)row * KDIM + pos * 4;
            dl = g_wlo + (size_t)row * KDIM + pos * 4;
        }
        const float4 v = *(const float4*)src;
        uint2 h, l;
        split2(v.x, v.y, h.x, l.x);
        split2(v.z, v.w, h.y, l.y);
        *(uint2*)dh = h;
        *(uint2*)dl = l;
    }
}

// ---------------------------------------------------------------------------
// Kernel 1: bf16 hi/lo tensor GEMM  h = A @ W^T + bias  (fp32 accum).
// BM=128, BN=48, BK=32, 256 threads (8 warps, 4m x 2n), cp.async 2-stage,
// ldmatrix fragment loads, 18 HMMA per kb.
// ---------------------------------------------------------------------------
#define BM 128
#define BN 48
#define BK 32
#define PITCH 40                 // bf16 per smem row (80 B)
#define ABUF_B (BM * PITCH * 2)  // 10240
#define BBUF_B (BN * PITCH * 2)  // 3840
#define AHI_B 0
#define ALO_B ABUF_B
#define BHI_B (2 * ABUF_B)
#define BLO_B (2 * ABUF_B + BBUF_B)
#define STAGE_B (2 * ABUF_B + 2 * BBUF_B)   // 28160
#define SMEM_DYN (2 * STAGE_B)              // 56320
#define NKT (KDIM / BK)                     // 16

__device__ __forceinline__ uint32_t s2u(const void* p) {
    uint32_t a;
    asm("{ .reg .u64 t; cvta.to.shared.u64 t, %1; cvt.u32.u64 %0, t; }"
        : "=r"(a) : "l"(p));
    return a;
}

#define CPA16(dst, src)                                                   \
    asm volatile("cp.async.ca.shared.global [%0], [%1], 16;"              \
                 :: "r"(dst), "l"(src) : "memory")

#define LDSM4(r0, r1, r2, r3, addr)                                       \
    asm volatile("ldmatrix.sync.aligned.m8n8.x4.shared.b16 "              \
                 "{%0,%1,%2,%3}, [%4];"                                   \
                 : "=r"(r0), "=r"(r1), "=r"(r2), "=r"(r3) : "r"(addr))

#define LDSM2(r0, r1, addr)                                               \
    asm volatile("ldmatrix.sync.aligned.m8n8.x2.shared.b16 "              \
                 "{%0,%1}, [%2];"                                         \
                 : "=r"(r0), "=r"(r1) : "r"(addr))

#define MMA_BF16(c, a, b0_, b1_)                                          \
    asm volatile(                                                         \
        "mma.sync.aligned.m16n8k16.row.col.f32.bf16.bf16.f32 "            \
        "{%0,%1,%2,%3}, {%4,%5,%6,%7}, {%8,%9}, {%0,%1,%2,%3};"           \
        : "+f"((c)[0]), "+f"((c)[1]), "+f"((c)[2]), "+f"((c)[3])          \
        : "r"((a)[0]), "r"((a)[1]), "r"((a)[2]), "r"((a)[3]),             \
          "r"(b0_), "r"(b1_))

__global__ __launch_bounds__(256, 2) void gemm_kernel(const float* __restrict__ bo)
{
    extern __shared__ __align__(16) char smem[];
    const uint32_t sbase = s2u(smem);

    const int tid = threadIdx.x;
    const int m0 = blockIdx.x * BM;
    const int n0 = blockIdx.y * BN;

    const int lane = tid & 31;
    const int grp = lane >> 2;
    const int qid = lane & 3;
    const int warpid = tid >> 5;
    const int wm = warpid & 3;   // m quadrant: rows wm*32
    const int wn = warpid >> 2;  // n half: cols wn*24

    // cp.async source pointers / dst offsets
    const int ac0 = tid, ac1 = tid + 256;          // A chunks (512 per buf)
    const __nv_bfloat16* ah_src0 = g_ahi + (size_t)(m0 + (ac0 >> 2)) * KDIM + (ac0 & 3) * 8;
    const __nv_bfloat16* ah_src1 = g_ahi + (size_t)(m0 + (ac1 >> 2)) * KDIM + (ac1 & 3) * 8;
    const __nv_bfloat16* al_src0 = g_alo + (size_t)(m0 + (ac0 >> 2)) * KDIM + (ac0 & 3) * 8;
    const __nv_bfloat16* al_src1 = g_alo + (size_t)(m0 + (ac1 >> 2)) * KDIM + (ac1 & 3) * 8;
    const uint32_t a_dst0 = (ac0 >> 2) * 80 + (ac0 & 3) * 16;
    const uint32_t a_dst1 = (ac1 >> 2) * 80 + (ac1 & 3) * 16;
    const bool hasB = (tid < 192);                 // B chunks (192 per buf)
    const int bc = hasB ? tid : 0;
    const __nv_bfloat16* bh_src = g_whi + (size_t)(n0 + (bc >> 2)) * KDIM + (bc & 3) * 8;
    const __nv_bfloat16* bl_src = g_wlo + (size_t)(n0 + (bc >> 2)) * KDIM + (bc & 3) * 8;
    const uint32_t b_dst = (bc >> 2) * 80 + (bc & 3) * 16;

#define CP_STAGE(ST, KT)                                                       \
    do {                                                                       \
        const int ko = (KT) * BK;                                              \
        const uint32_t sb = sbase + (ST) * STAGE_B;                            \
        CPA16(sb + AHI_B + a_dst0, ah_src0 + ko);                              \
        CPA16(sb + AHI_B + a_dst1, ah_src1 + ko);                              \
        CPA16(sb + ALO_B + a_dst0, al_src0 + ko);                              \
        CPA16(sb + ALO_B + a_dst1, al_src1 + ko);                              \
        if (hasB) {                                                            \
            CPA16(sb + BHI_B + b_dst, bh_src + ko);                            \
            CPA16(sb + BLO_B + b_dst, bl_src + ko);                            \
        }                                                                      \
        asm volatile("cp.async.commit_group;" ::: "memory");                   \
    } while (0)

    // ldmatrix lane address offsets (bytes within A / B buffers)
    const int lt = lane >> 3, lr = lane & 7;
    const uint32_t a_off = (uint32_t)((wm * 32 + (lt & 1) * 8 + lr) * 80 + (lt >> 1) * 16);
    const uint32_t b4_off = (uint32_t)((wn * 24 + (lt >> 1) * 8 + lr) * 80 + (lt & 1) * 16);
    const int l15 = lane & 15;
    const uint32_t b2_off = (uint32_t)((wn * 24 + 16 + (l15 & 7)) * 80 + ((l15 >> 3) & 1) * 16);

    float acc[2][3][4];
#pragma unroll
    for (int ma = 0; ma < 2; ma++)
#pragma unroll
        for (int j = 0; j < 3; j++)
#pragma unroll
            for (int c = 0; c < 4; c++) acc[ma][j][c] = 0.0f;

#define COMPUTE(ST)                                                            \
    do {                                                                       \
        const uint32_t sb = sbase + (ST) * STAGE_B;                            \
        _Pragma("unroll")                                                      \
        for (int kb = 0; kb < BK; kb += 16) {                                  \
            unsigned ah[2][4], al[2][4], bh[3][2], bl[3][2];                   \
            _Pragma("unroll")                                                  \
            for (int ma = 0; ma < 2; ma++) {                                   \
                const uint32_t aa = sb + a_off + ma * 1280 + kb * 2;           \
                LDSM4(ah[ma][0], ah[ma][1], ah[ma][2], ah[ma][3], aa + AHI_B); \
                LDSM4(al[ma][0], al[ma][1], al[ma][2], al[ma][3], aa + ALO_B); \
            }                                                                  \
            {                                                                  \
                const uint32_t b4 = sb + b4_off + kb * 2;                      \
                const uint32_t b2 = sb + b2_off + kb * 2;                      \
                LDSM4(bh[0][0], bh[0][1], bh[1][0], bh[1][1], b4 + BHI_B);     \
                LDSM2(bh[2][0], bh[2][1], b2 + BHI_B);                         \
                LDSM4(bl[0][0], bl[0][1], bl[1][0], bl[1][1], b4 + BLO_B);     \
                LDSM2(bl[2][0], bl[2][1], b2 + BLO_B);                         \
            }                                                                  \
            _Pragma("unroll")                                                  \
            for (int ma = 0; ma < 2; ma++)                                     \
                _Pragma("unroll")                                              \
                for (int j = 0; j < 3; j++) {                                  \
                    MMA_BF16(acc[ma][j], ah[ma], bh[j][0], bh[j][1]);          \
                    MMA_BF16(acc[ma][j], ah[ma], bl[j][0], bl[j][1]);          \
                    MMA_BF16(acc[ma][j], al[ma], bh[j][0], bh[j][1]);          \
                }                                                              \
        }                                                                      \
    } while (0)

    // Pipeline: 2-stage cp.async double buffer
    CP_STAGE(0, 0);
    asm volatile("cp.async.wait_group 0;" ::: "memory");
    __syncthreads();

#pragma unroll 1
    for (int kt = 0; kt < NKT; kt++) {
        if (kt < NKT - 1) CP_STAGE((kt + 1) & 1, kt + 1);
        COMPUTE(kt & 1);
        asm volatile("cp.async.wait_group 0;" ::: "memory");
        __syncthreads();
    }

    // Epilogue: add bias, store fp32 h
#pragma unroll
    for (int j = 0; j < 3; j++) {
        const int col = n0 + wn * 24 + j * 8 + qid * 2;
        const float2 bj = *(const float2*)(bo + col);
#pragma unroll
        for (int ma = 0; ma < 2; ma++) {
            const int row0 = m0 + wm * 32 + ma * 16 + grp;
            float2 v0, v1;
            v0.x = acc[ma][j][0] + bj.x;
            v0.y = acc[ma][j][1] + bj.y;
            v1.x = acc[ma][j][2] + bj.x;
            v1.y = acc[ma][j][3] + bj.y;
            *(float2*)(g_h + (size_t)row0 * NOUT + col) = v0;
            *(float2*)(g_h + (size_t)(row0 + 8) * NOUT + col) = v1;
        }
    }
}

// ---------------------------------------------------------------------------
// Kernel 2: masked cumsum over sequence -> prefix [B, N+1, 480]
// ---------------------------------------------------------------------------
__global__ __launch_bounds__(120) void prefix_kernel(const int* __restrict__ lengths)
{
    const int b = blockIdx.y;
    const int o = blockIdx.x * 120 + threadIdx.x;
    const int len = lengths[b];
    float acc = 0.0f;
    g_prefix[((size_t)b * NP1 + 0) * NOUT + o] = 0.0f;
#pragma unroll 8
    for (int n = 0; n < Nn; n++) {
        const float v = g_h[((size_t)b * Nn + n) * NOUT + o];
        if (n < len) acc += v;
        g_prefix[((size_t)b * NP1 + n + 1) * NOUT + o] = acc;
    }
}

// ---------------------------------------------------------------------------
// Kernel 3: span features + L2 norm, smem-tiled over 8x8 (l, r) tiles.
// ---------------------------------------------------------------------------
#define STH 256

__global__ __launch_bounds__(STH) void span_kernel(float* __restrict__ out)
{
    __shared__ float sL[8][NOUT];
    __shared__ float sR[8][NOUT];

    const int b = blockIdx.y;
    const int t = blockIdx.x;                 // 0..35, t = rt*(rt+1)/2 + lt
    int rt = 0;
    while ((rt + 1) * (rt + 2) / 2 <= t) rt++;
    const int lt = t - rt * (rt + 1) / 2;

    const int tid = threadIdx.x;
    const float* pb = g_prefix + (size_t)b * NP1 * NOUT;

    for (int i4 = tid; i4 < 16 * (NOUT / 4); i4 += STH) {
        const int row = i4 / (NOUT / 4);
        const int pos = i4 % (NOUT / 4);
        const int grow = (row < 8) ? (lt * 8 + row) : (rt * 8 + (row - 8) + 1);
        const float4 v = *(const float4*)(pb + (size_t)grow * NOUT + pos * 4);
        if (row < 8) *(float4*)&sL[row][pos * 4] = v;
        else         *(float4*)&sR[row - 8][pos * 4] = v;
    }
    __syncthreads();

    const int slot = tid / 60;        // 0..3 active, 4 = spare
    const int lane = tid % 60;
    const int base = (slot < 4) ? slot : 0;
    const bool diag = (lt == rt);

#pragma unroll 4
    for (int i = 0; i < 16; i++) {
        const int sp = base + 4 * i;          // 0..63
        const int li = sp & 7;
        const int ri = sp >> 3;

        const float4* Rp = (const float4*)&sR[ri][0];
        const float4* Lp = (const float4*)&sL[li][0];
        const float4 ra = Rp[lane],      la = Lp[lane];
        const float4 rb = Rp[60 + lane], lb = Lp[60 + lane];

        float4 da, db;
        da.x = ra.x - la.x; da.y = ra.y - la.y; da.z = ra.z - la.z; da.w = ra.w - la.w;
        db.x = rb.x - lb.x; db.y = rb.y - lb.y; db.z = rb.z - lb.z; db.w = rb.w - lb.w;

        float sqA = da.x * da.x;
        sqA = fmaf(da.y, da.y, sqA); sqA = fmaf(da.z, da.z, sqA); sqA = fmaf(da.w, da.w, sqA);
        float sqB = db.x * db.x;
        sqB = fmaf(db.y, db.y, sqB); sqB = fmaf(db.z, db.z, sqB); sqB = fmaf(db.w, db.w, sqB);

        sqA += __shfl_xor_sync(0xffffffffu, sqA, 1);
        sqA += __shfl_xor_sync(0xffffffffu, sqA, 2);
        sqB += __shfl_xor_sync(0xffffffffu, sqB, 1);
        sqB += __shfl_xor_sync(0xffffffffu, sqB, 2);

        const float invA = rsqrtf(sqA);
        const float invB = rsqrtf(sqB);

        if (slot < 4 && (!diag || li < ri)) {
            const int l = lt * 8 + li;
            const int r = rt * 8 + ri;
            const int k = r - l;
            const int s = (((k - 1) * (128 - k)) >> 1) + l;
            float* op = out + (size_t)(b * NSPAN + s) * NOUT;
            float4 oa, ob;
            oa.x = da.x * invA; oa.y = da.y * invA; oa.z = da.z * invA; oa.w = da.w * invA;
            ob.x = db.x * invB; ob.y = db.y * invB; ob.z = db.z * invB; ob.w = db.w * invB;
            *(float4*)(op + lane * 4) = oa;
            *(float4*)(op + 240 + lane * 4) = ob;
        }
    }
}

// ---------------------------------------------------------------------------
extern "C" void kernel_launch(void* const* d_in, const int* in_sizes, int n_in,
                              void* d_out, int out_size)
{
    const int*   x       = (const int*)d_in[0];
    const int*   lengths = (const int*)d_in[1];
    const float* emb     = (const float*)d_in[2];
    const float* w_out   = (const float*)d_in[3];
    const float* b_out   = (const float*)d_in[4];
    float* out = (float*)d_out;

    cudaFuncSetAttribute(gemm_kernel,
                         cudaFuncAttributeMaxDynamicSharedMemorySize, SMEM_DYN);

    prep_kernel<<<572, 256>>>(x, emb, w_out);
    gemm_kernel<<<dim3(ROWS / BM, NOUT / BN), 256, SMEM_DYN>>>(b_out);
    prefix_kernel<<<dim3(4, Bb), 120>>>(lengths);
    span_kernel<<<dim3(36, Bb), STH>>>(out);
}

// round 15
// speedup vs baseline: 1.2442x; 1.1810x over previous
#include <cuda_runtime.h>
#include <cuda_bf16.h>
#include <cstdint>

#define Bb 64
#define Nn 64
#define KDIM 512
#define NOUT 480           // NT*SEM = 30*16
#define ROWS 4096
#define NSPAN 2016
#define NP1 65

// Scratch — __device__ globals (no allocation allowed)
__device__ float g_prefix[Bb * NP1 * NOUT];        // 7.99 MB
__device__ __nv_bfloat16 g_ahi[ROWS * KDIM];       // 4 MB
__device__ __nv_bfloat16 g_alo[ROWS * KDIM];       // 4 MB
__device__ __nv_bfloat16 g_whi[NOUT * KDIM];       // 0.5 MB
__device__ __nv_bfloat16 g_wlo[NOUT * KDIM];       // 0.5 MB

__device__ __forceinline__ void split2(float x, float y, unsigned& hi, unsigned& lo) {
    // hi = {bf16(y), bf16(x)} with x in low half
    asm("cvt.rn.bf16x2.f32 %0, %1, %2;" : "=r"(hi) : "f"(y), "f"(x));
    const float rx = x - __uint_as_float(hi << 16);
    const float ry = y - __uint_as_float(hi & 0xffff0000u);
    asm("cvt.rn.bf16x2.f32 %0, %1, %2;" : "=r"(lo) : "f"(ry), "f"(rx));
}

// ---------------------------------------------------------------------------
// Kernel 0: gather + hi/lo split of A (emb[x]) and W into bf16 buffers.
// Blocks 0..511: A (8 rows each). Blocks 512..571: W (8 rows each).
// ---------------------------------------------------------------------------
__global__ __launch_bounds__(256) void prep_kernel(
    const int* __restrict__ x, const float* __restrict__ emb,
    const float* __restrict__ w)
{
    const int blk = blockIdx.x;
    const int tid = threadIdx.x;
    const bool isA = (blk < 512);
    const int rbase = (isA ? blk : (blk - 512)) * 8;

#pragma unroll
    for (int i = 0; i < 4; i++) {
        const int idx = tid + i * 256;          // 1024 float4 per block
        const int r8 = idx >> 7;                // 0..7
        const int pos = idx & 127;              // float4 index in row
        const int row = rbase + r8;
        const float* src;
        __nv_bfloat16 *dh, *dl;
        if (isA) {
            src = emb + (size_t)x[row] * KDIM + pos * 4;
            dh = g_ahi + (size_t)row * KDIM + pos * 4;
            dl = g_alo + (size_t)row * KDIM + pos * 4;
        } else {
            src = w + (size_t)row * KDIM + pos * 4;
            dh = g_whi + (size_t)row * KDIM + pos * 4;
            dl = g_wlo + (size_t)row * KDIM + pos * 4;
        }
        const float4 v = *(const float4*)src;
        uint2 h, l;
        split2(v.x, v.y, h.x, l.x);
        split2(v.z, v.w, h.y, l.y);
        *(uint2*)dh = h;
        *(uint2*)dl = l;
    }
}

// ---------------------------------------------------------------------------
// Kernel 1: bf16 hi/lo tensor GEMM + FUSED masked cumsum -> g_prefix.
// BM=128 (= 2 whole batches), BN=48, BK=32, 256 threads, cp.async 2-stage,
// ldmatrix fragments. Epilogue: stage acc to smem, 96 threads scan 64 rows
// per (batch, col) and write prefix directly (h tensor never materialized).
// ---------------------------------------------------------------------------
#define BM 128
#define BN 48
#define BK 32
#define PITCH 40                 // bf16 per smem row (80 B)
#define ABUF_B (BM * PITCH * 2)  // 10240
#define BBUF_B (BN * PITCH * 2)  // 3840
#define AHI_B 0
#define ALO_B ABUF_B
#define BHI_B (2 * ABUF_B)
#define BLO_B (2 * ABUF_B + BBUF_B)
#define STAGE_B (2 * ABUF_B + 2 * BBUF_B)   // 28160
#define SMEM_DYN (2 * STAGE_B)              // 56320
#define NKT (KDIM / BK)                     // 16
#define SPITCH 50                           // stage pitch (floats)

__device__ __forceinline__ uint32_t s2u(const void* p) {
    uint32_t a;
    asm("{ .reg .u64 t; cvta.to.shared.u64 t, %1; cvt.u32.u64 %0, t; }"
        : "=r"(a) : "l"(p));
    return a;
}

#define CPA16(dst, src)                                                   \
    asm volatile("cp.async.ca.shared.global [%0], [%1], 16;"              \
                 :: "r"(dst), "l"(src) : "memory")

#define LDSM4(r0, r1, r2, r3, addr)                                       \
    asm volatile("ldmatrix.sync.aligned.m8n8.x4.shared.b16 "              \
                 "{%0,%1,%2,%3}, [%4];"                                   \
                 : "=r"(r0), "=r"(r1), "=r"(r2), "=r"(r3) : "r"(addr))

#define LDSM2(r0, r1, addr)                                               \
    asm volatile("ldmatrix.sync.aligned.m8n8.x2.shared.b16 "              \
                 "{%0,%1}, [%2];"                                         \
                 : "=r"(r0), "=r"(r1) : "r"(addr))

#define MMA_BF16(c, a, b0_, b1_)                                          \
    asm volatile(                                                         \
        "mma.sync.aligned.m16n8k16.row.col.f32.bf16.bf16.f32 "            \
        "{%0,%1,%2,%3}, {%4,%5,%6,%7}, {%8,%9}, {%0,%1,%2,%3};"           \
        : "+f"((c)[0]), "+f"((c)[1]), "+f"((c)[2]), "+f"((c)[3])          \
        : "r"((a)[0]), "r"((a)[1]), "r"((a)[2]), "r"((a)[3]),             \
          "r"(b0_), "r"(b1_))

__global__ __launch_bounds__(256, 2) void gemm_kernel(
    const float* __restrict__ bo, const int* __restrict__ lengths)
{
    extern __shared__ __align__(16) char smem[];
    const uint32_t sbase = s2u(smem);

    const int tid = threadIdx.x;
    const int m0 = blockIdx.x * BM;
    const int n0 = blockIdx.y * BN;

    const int lane = tid & 31;
    const int grp = lane >> 2;
    const int qid = lane & 3;
    const int warpid = tid >> 5;
    const int wm = warpid & 3;   // m quadrant: rows wm*32
    const int wn = warpid >> 2;  // n half: cols wn*24

    // cp.async source pointers / dst offsets
    const int ac0 = tid, ac1 = tid + 256;          // A chunks (512 per buf)
    const __nv_bfloat16* ah_src0 = g_ahi + (size_t)(m0 + (ac0 >> 2)) * KDIM + (ac0 & 3) * 8;
    const __nv_bfloat16* ah_src1 = g_ahi + (size_t)(m0 + (ac1 >> 2)) * KDIM + (ac1 & 3) * 8;
    const __nv_bfloat16* al_src0 = g_alo + (size_t)(m0 + (ac0 >> 2)) * KDIM + (ac0 & 3) * 8;
    const __nv_bfloat16* al_src1 = g_alo + (size_t)(m0 + (ac1 >> 2)) * KDIM + (ac1 & 3) * 8;
    const uint32_t a_dst0 = (ac0 >> 2) * 80 + (ac0 & 3) * 16;
    const uint32_t a_dst1 = (ac1 >> 2) * 80 + (ac1 & 3) * 16;
    const bool hasB = (tid < 192);                 // B chunks (192 per buf)
    const int bc = hasB ? tid : 0;
    const __nv_bfloat16* bh_src = g_whi + (size_t)(n0 + (bc >> 2)) * KDIM + (bc & 3) * 8;
    const __nv_bfloat16* bl_src = g_wlo + (size_t)(n0 + (bc >> 2)) * KDIM + (bc & 3) * 8;
    const uint32_t b_dst = (bc >> 2) * 80 + (bc & 3) * 16;

#define CP_STAGE(ST, KT)                                                       \
    do {                                                                       \
        const int ko = (KT) * BK;                                              \
        const uint32_t sb = sbase + (ST) * STAGE_B;                            \
        CPA16(sb + AHI_B + a_dst0, ah_src0 + ko);                              \
        CPA16(sb + AHI_B + a_dst1, ah_src1 + ko);                              \
        CPA16(sb + ALO_B + a_dst0, al_src0 + ko);                              \
        CPA16(sb + ALO_B + a_dst1, al_src1 + ko);                              \
        if (hasB) {                                                            \
            CPA16(sb + BHI_B + b_dst, bh_src + ko);                            \
            CPA16(sb + BLO_B + b_dst, bl_src + ko);                            \
        }                                                                      \
        asm volatile("cp.async.commit_group;" ::: "memory");                   \
    } while (0)

    // ldmatrix lane address offsets (bytes within A / B buffers)
    const int lt = lane >> 3, lr = lane & 7;
    const uint32_t a_off = (uint32_t)((wm * 32 + (lt & 1) * 8 + lr) * 80 + (lt >> 1) * 16);
    const uint32_t b4_off = (uint32_t)((wn * 24 + (lt >> 1) * 8 + lr) * 80 + (lt & 1) * 16);
    const int l15 = lane & 15;
    const uint32_t b2_off = (uint32_t)((wn * 24 + 16 + (l15 & 7)) * 80 + ((l15 >> 3) & 1) * 16);

    float acc[2][3][4];
#pragma unroll
    for (int ma = 0; ma < 2; ma++)
#pragma unroll
        for (int j = 0; j < 3; j++)
#pragma unroll
            for (int c = 0; c < 4; c++) acc[ma][j][c] = 0.0f;

#define COMPUTE(ST)                                                            \
    do {                                                                       \
        const uint32_t sb = sbase + (ST) * STAGE_B;                            \
        _Pragma("unroll")                                                      \
        for (int kb = 0; kb < BK; kb += 16) {                                  \
            unsigned ah[2][4], al[2][4], bh[3][2], bl[3][2];                   \
            _Pragma("unroll")                                                  \
            for (int ma = 0; ma < 2; ma++) {                                   \
                const uint32_t aa = sb + a_off + ma * 1280 + kb * 2;           \
                LDSM4(ah[ma][0], ah[ma][1], ah[ma][2], ah[ma][3], aa + AHI_B); \
                LDSM4(al[ma][0], al[ma][1], al[ma][2], al[ma][3], aa + ALO_B); \
            }                                                                  \
            {                                                                  \
                const uint32_t b4 = sb + b4_off + kb * 2;                      \
                const uint32_t b2 = sb + b2_off + kb * 2;                      \
                LDSM4(bh[0][0], bh[0][1], bh[1][0], bh[1][1], b4 + BHI_B);     \
                LDSM2(bh[2][0], bh[2][1], b2 + BHI_B);                         \
                LDSM4(bl[0][0], bl[0][1], bl[1][0], bl[1][1], b4 + BLO_B);     \
                LDSM2(bl[2][0], bl[2][1], b2 + BLO_B);                         \
            }                                                                  \
            _Pragma("unroll")                                                  \
            for (int ma = 0; ma < 2; ma++)                                     \
                _Pragma("unroll")                                              \
                for (int j = 0; j < 3; j++) {                                  \
                    MMA_BF16(acc[ma][j], ah[ma], bh[j][0], bh[j][1]);          \
                    MMA_BF16(acc[ma][j], ah[ma], bl[j][0], bl[j][1]);          \
                    MMA_BF16(acc[ma][j], al[ma], bh[j][0], bh[j][1]);          \
                }                                                              \
        }                                                                      \
    } while (0)

    // Pipeline: 2-stage cp.async double buffer
    CP_STAGE(0, 0);
    asm volatile("cp.async.wait_group 0;" ::: "memory");
    __syncthreads();

#pragma unroll 1
    for (int kt = 0; kt < NKT; kt++) {
        if (kt < NKT - 1) CP_STAGE((kt + 1) & 1, kt + 1);
        COMPUTE(kt & 1);
        asm volatile("cp.async.wait_group 0;" ::: "memory");
        __syncthreads();
    }

    // ---- Fused epilogue: stage acc -> smem, then masked cumsum -> g_prefix
    float* stage = (float*)smem;   // [128][SPITCH]
#pragma unroll
    for (int j = 0; j < 3; j++) {
        const int col = wn * 24 + j * 8 + qid * 2;
#pragma unroll
        for (int ma = 0; ma < 2; ma++) {
            const int r0 = wm * 32 + ma * 16 + grp;
            stage[r0 * SPITCH + col]           = acc[ma][j][0];
            stage[r0 * SPITCH + col + 1]       = acc[ma][j][1];
            stage[(r0 + 8) * SPITCH + col]     = acc[ma][j][2];
            stage[(r0 + 8) * SPITCH + col + 1] = acc[ma][j][3];
        }
    }
    __syncthreads();

    if (tid < 96) {
        const int bb = tid / 48;               // which of the 2 batches
        const int col = tid % 48;
        const int batch = (m0 >> 6) + bb;
        const int len = lengths[batch];
        const int gcol = n0 + col;
        const float bias = bo[gcol];
        float accu = 0.0f;
        float* gp = g_prefix + (size_t)(batch * NP1) * NOUT + gcol;
        gp[0] = 0.0f;
#pragma unroll 4
        for (int n = 0; n < Nn; n++) {
            const float v = stage[(bb * Nn + n) * SPITCH + col] + bias;
            if (n < len) accu += v;
            gp[(size_t)(n + 1) * NOUT] = accu;
        }
    }
}

// ---------------------------------------------------------------------------
// Kernel 3: span features + L2 norm, smem-tiled over 8x8 (l, r) tiles.
// ---------------------------------------------------------------------------
#define STH 256

__global__ __launch_bounds__(STH) void span_kernel(float* __restrict__ out)
{
    __shared__ float sL[8][NOUT];
    __shared__ float sR[8][NOUT];

    const int b = blockIdx.y;
    const int t = blockIdx.x;                 // 0..35, t = rt*(rt+1)/2 + lt
    int rt = 0;
    while ((rt + 1) * (rt + 2) / 2 <= t) rt++;
    const int lt = t - rt * (rt + 1) / 2;

    const int tid = threadIdx.x;
    const float* pb = g_prefix + (size_t)b * NP1 * NOUT;

    for (int i4 = tid; i4 < 16 * (NOUT / 4); i4 += STH) {
        const int row = i4 / (NOUT / 4);
        const int pos = i4 % (NOUT / 4);
        const int grow = (row < 8) ? (lt * 8 + row) : (rt * 8 + (row - 8) + 1);
        const float4 v = *(const float4*)(pb + (size_t)grow * NOUT + pos * 4);
        if (row < 8) *(float4*)&sL[row][pos * 4] = v;
        else         *(float4*)&sR[row - 8][pos * 4] = v;
    }
    __syncthreads();

    const int slot = tid / 60;        // 0..3 active, 4 = spare
    const int lane = tid % 60;
    const int base = (slot < 4) ? slot : 0;
    const bool diag = (lt == rt);

#pragma unroll 4
    for (int i = 0; i < 16; i++) {
        const int sp = base + 4 * i;          // 0..63
        const int li = sp & 7;
        const int ri = sp >> 3;

        const float4* Rp = (const float4*)&sR[ri][0];
        const float4* Lp = (const float4*)&sL[li][0];
        const float4 ra = Rp[lane],      la = Lp[lane];
        const float4 rb = Rp[60 + lane], lb = Lp[60 + lane];

        float4 da, db;
        da.x = ra.x - la.x; da.y = ra.y - la.y; da.z = ra.z - la.z; da.w = ra.w - la.w;
        db.x = rb.x - lb.x; db.y = rb.y - lb.y; db.z = rb.z - lb.z; db.w = rb.w - lb.w;

        float sqA = da.x * da.x;
        sqA = fmaf(da.y, da.y, sqA); sqA = fmaf(da.z, da.z, sqA); sqA = fmaf(da.w, da.w, sqA);
        float sqB = db.x * db.x;
        sqB = fmaf(db.y, db.y, sqB); sqB = fmaf(db.z, db.z, sqB); sqB = fmaf(db.w, db.w, sqB);

        sqA += __shfl_xor_sync(0xffffffffu, sqA, 1);
        sqA += __shfl_xor_sync(0xffffffffu, sqA, 2);
        sqB += __shfl_xor_sync(0xffffffffu, sqB, 1);
        sqB += __shfl_xor_sync(0xffffffffu, sqB, 2);

        const float invA = rsqrtf(sqA);
        const float invB = rsqrtf(sqB);

        if (slot < 4 && (!diag || li < ri)) {
            const int l = lt * 8 + li;
            const int r = rt * 8 + ri;
            const int k = r - l;
            const int s = (((k - 1) * (128 - k)) >> 1) + l;
            float* op = out + (size_t)(b * NSPAN + s) * NOUT;
            float4 oa, ob;
            oa.x = da.x * invA; oa.y = da.y * invA; oa.z = da.z * invA; oa.w = da.w * invA;
            ob.x = db.x * invB; ob.y = db.y * invB; ob.z = db.z * invB; ob.w = db.w * invB;
            *(float4*)(op + lane * 4) = oa;
            *(float4*)(op + 240 + lane * 4) = ob;
        }
    }
}

// ---------------------------------------------------------------------------
extern "C" void kernel_launch(void* const* d_in, const int* in_sizes, int n_in,
                              void* d_out, int out_size)
{
    const int*   x       = (const int*)d_in[0];
    const int*   lengths = (const int*)d_in[1];
    const float* emb     = (const float*)d_in[2];
    const float* w_out   = (const float*)d_in[3];
    const float* b_out   = (const float*)d_in[4];
    float* out = (float*)d_out;

    cudaFuncSetAttribute(gemm_kernel,
                         cudaFuncAttributeMaxDynamicSharedMemorySize, SMEM_DYN);

    prep_kernel<<<572, 256>>>(x, emb, w_out);
    gemm_kernel<<<dim3(ROWS / BM, NOUT / BN), 256, SMEM_DYN>>>(b_out, lengths);
    span_kernel<<<dim3(36, Bb), STH>>>(out);
}

// round 16
// speedup vs baseline: 1.2704x; 1.0210x over previous
#include <cuda_runtime.h>
#include <cuda_bf16.h>
#include <cstdint>

#define Bb 64
#define Nn 64
#define KDIM 512
#define NOUT 480           // NT*SEM = 30*16
#define ROWS 4096
#define NSPAN 2016
#define NP1 65

// Scratch — __device__ globals (no allocation allowed)
__device__ float g_prefix[Bb * NP1 * NOUT];        // 7.99 MB
__device__ __nv_bfloat16 g_ahi[ROWS * KDIM];       // 4 MB
__device__ __nv_bfloat16 g_alo[ROWS * KDIM];       // 4 MB
__device__ __nv_bfloat16 g_whi[NOUT * KDIM];       // 0.5 MB
__device__ __nv_bfloat16 g_wlo[NOUT * KDIM];       // 0.5 MB

__device__ __forceinline__ void split2(float x, float y, unsigned& hi, unsigned& lo) {
    // hi = {bf16(y), bf16(x)} with x in low half
    asm("cvt.rn.bf16x2.f32 %0, %1, %2;" : "=r"(hi) : "f"(y), "f"(x));
    const float rx = x - __uint_as_float(hi << 16);
    const float ry = y - __uint_as_float(hi & 0xffff0000u);
    asm("cvt.rn.bf16x2.f32 %0, %1, %2;" : "=r"(lo) : "f"(ry), "f"(rx));
}

// ---------------------------------------------------------------------------
// Kernel 0: gather + hi/lo split of A (emb[x]) and W into bf16 buffers.
// ---------------------------------------------------------------------------
__global__ __launch_bounds__(256) void prep_kernel(
    const int* __restrict__ x, const float* __restrict__ emb,
    const float* __restrict__ w)
{
    const int blk = blockIdx.x;
    const int tid = threadIdx.x;
    const bool isA = (blk < 512);
    const int rbase = (isA ? blk : (blk - 512)) * 8;

#pragma unroll
    for (int i = 0; i < 4; i++) {
        const int idx = tid + i * 256;          // 1024 float4 per block
        const int r8 = idx >> 7;
        const int pos = idx & 127;
        const int row = rbase + r8;
        const float* src;
        __nv_bfloat16 *dh, *dl;
        if (isA) {
            src = emb + (size_t)x[row] * KDIM + pos * 4;
            dh = g_ahi + (size_t)row * KDIM + pos * 4;
            dl = g_alo + (size_t)row * KDIM + pos * 4;
        } else {
            src = w + (size_t)row * KDIM + pos * 4;
            dh = g_whi + (size_t)row * KDIM + pos * 4;
            dl = g_wlo + (size_t)row * KDIM + pos * 4;
        }
        const float4 v = *(const float4*)src;
        uint2 h, l;
        split2(v.x, v.y, h.x, l.x);
        split2(v.z, v.w, h.y, l.y);
        *(uint2*)dh = h;
        *(uint2*)dl = l;
    }
}

// ---------------------------------------------------------------------------
// Kernel 1: bf16 hi/lo tensor GEMM + FUSED masked cumsum -> g_prefix.
// ---------------------------------------------------------------------------
#define BM 128
#define BN 48
#define BK 32
#define PITCH 40
#define ABUF_B (BM * PITCH * 2)  // 10240
#define BBUF_B (BN * PITCH * 2)  // 3840
#define AHI_B 0
#define ALO_B ABUF_B
#define BHI_B (2 * ABUF_B)
#define BLO_B (2 * ABUF_B + BBUF_B)
#define STAGE_B (2 * ABUF_B + 2 * BBUF_B)   // 28160
#define SMEM_DYN (2 * STAGE_B)              // 56320
#define NKT (KDIM / BK)                     // 16
#define SPITCH 50

__device__ __forceinline__ uint32_t s2u(const void* p) {
    uint32_t a;
    asm("{ .reg .u64 t; cvta.to.shared.u64 t, %1; cvt.u32.u64 %0, t; }"
        : "=r"(a) : "l"(p));
    return a;
}

#define CPA16(dst, src)                                                   \
    asm volatile("cp.async.ca.shared.global [%0], [%1], 16;"              \
                 :: "r"(dst), "l"(src) : "memory")

#define LDSM4(r0, r1, r2, r3, addr)                                       \
    asm volatile("ldmatrix.sync.aligned.m8n8.x4.shared.b16 "              \
                 "{%0,%1,%2,%3}, [%4];"                                   \
                 : "=r"(r0), "=r"(r1), "=r"(r2), "=r"(r3) : "r"(addr))

#define LDSM2(r0, r1, addr)                                               \
    asm volatile("ldmatrix.sync.aligned.m8n8.x2.shared.b16 "              \
                 "{%0,%1}, [%2];"                                         \
                 : "=r"(r0), "=r"(r1) : "r"(addr))

#define MMA_BF16(c, a, b0_, b1_)                                          \
    asm volatile(                                                         \
        "mma.sync.aligned.m16n8k16.row.col.f32.bf16.bf16.f32 "            \
        "{%0,%1,%2,%3}, {%4,%5,%6,%7}, {%8,%9}, {%0,%1,%2,%3};"           \
        : "+f"((c)[0]), "+f"((c)[1]), "+f"((c)[2]), "+f"((c)[3])          \
        : "r"((a)[0]), "r"((a)[1]), "r"((a)[2]), "r"((a)[3]),             \
          "r"(b0_), "r"(b1_))

__global__ __launch_bounds__(256, 2) void gemm_kernel(
    const float* __restrict__ bo, const int* __restrict__ lengths)
{
    extern __shared__ __align__(16) char smem[];
    const uint32_t sbase = s2u(smem);

    const int tid = threadIdx.x;
    const int m0 = blockIdx.x * BM;
    const int n0 = blockIdx.y * BN;

    const int lane = tid & 31;
    const int grp = lane >> 2;
    const int qid = lane & 3;
    const int warpid = tid >> 5;
    const int wm = warpid & 3;
    const int wn = warpid >> 2;

    const int ac0 = tid, ac1 = tid + 256;
    const __nv_bfloat16* ah_src0 = g_ahi + (size_t)(m0 + (ac0 >> 2)) * KDIM + (ac0 & 3) * 8;
    const __nv_bfloat16* ah_src1 = g_ahi + (size_t)(m0 + (ac1 >> 2)) * KDIM + (ac1 & 3) * 8;
    const __nv_bfloat16* al_src0 = g_alo + (size_t)(m0 + (ac0 >> 2)) * KDIM + (ac0 & 3) * 8;
    const __nv_bfloat16* al_src1 = g_alo + (size_t)(m0 + (ac1 >> 2)) * KDIM + (ac1 & 3) * 8;
    const uint32_t a_dst0 = (ac0 >> 2) * 80 + (ac0 & 3) * 16;
    const uint32_t a_dst1 = (ac1 >> 2) * 80 + (ac1 & 3) * 16;
    const bool hasB = (tid < 192);
    const int bc = hasB ? tid : 0;
    const __nv_bfloat16* bh_src = g_whi + (size_t)(n0 + (bc >> 2)) * KDIM + (bc & 3) * 8;
    const __nv_bfloat16* bl_src = g_wlo + (size_t)(n0 + (bc >> 2)) * KDIM + (bc & 3) * 8;
    const uint32_t b_dst = (bc >> 2) * 80 + (bc & 3) * 16;

#define CP_STAGE(ST, KT)                                                       \
    do {                                                                       \
        const int ko = (KT) * BK;                                              \
        const uint32_t sb = sbase + (ST) * STAGE_B;                            \
        CPA16(sb + AHI_B + a_dst0, ah_src0 + ko);                              \
        CPA16(sb + AHI_B + a_dst1, ah_src1 + ko);                              \
        CPA16(sb + ALO_B + a_dst0, al_src0 + ko);                              \
        CPA16(sb + ALO_B + a_dst1, al_src1 + ko);                              \
        if (hasB) {                                                            \
            CPA16(sb + BHI_B + b_dst, bh_src + ko);                            \
            CPA16(sb + BLO_B + b_dst, bl_src + ko);                            \
        }                                                                      \
        asm volatile("cp.async.commit_group;" ::: "memory");                   \
    } while (0)

    const int lt = lane >> 3, lr = lane & 7;
    const uint32_t a_off = (uint32_t)((wm * 32 + (lt & 1) * 8 + lr) * 80 + (lt >> 1) * 16);
    const uint32_t b4_off = (uint32_t)((wn * 24 + (lt >> 1) * 8 + lr) * 80 + (lt & 1) * 16);
    const int l15 = lane & 15;
    const uint32_t b2_off = (uint32_t)((wn * 24 + 16 + (l15 & 7)) * 80 + ((l15 >> 3) & 1) * 16);

    float acc[2][3][4];
#pragma unroll
    for (int ma = 0; ma < 2; ma++)
#pragma unroll
        for (int j = 0; j < 3; j++)
#pragma unroll
            for (int c = 0; c < 4; c++) acc[ma][j][c] = 0.0f;

#define COMPUTE(ST)                                                            \
    do {                                                                       \
        const uint32_t sb = sbase + (ST) * STAGE_B;                            \
        _Pragma("unroll")                                                      \
        for (int kb = 0; kb < BK; kb += 16) {                                  \
            unsigned ah[2][4], al[2][4], bh[3][2], bl[3][2];                   \
            _Pragma("unroll")                                                  \
            for (int ma = 0; ma < 2; ma++) {                                   \
                const uint32_t aa = sb + a_off + ma * 1280 + kb * 2;           \
                LDSM4(ah[ma][0], ah[ma][1], ah[ma][2], ah[ma][3], aa + AHI_B); \
                LDSM4(al[ma][0], al[ma][1], al[ma][2], al[ma][3], aa + ALO_B); \
            }                                                                  \
            {                                                                  \
                const uint32_t b4 = sb + b4_off + kb * 2;                      \
                const uint32_t b2 = sb + b2_off + kb * 2;                      \
                LDSM4(bh[0][0], bh[0][1], bh[1][0], bh[1][1], b4 + BHI_B);     \
                LDSM2(bh[2][0], bh[2][1], b2 + BHI_B);                         \
                LDSM4(bl[0][0], bl[0][1], bl[1][0], bl[1][1], b4 + BLO_B);     \
                LDSM2(bl[2][0], bl[2][1], b2 + BLO_B);                         \
            }                                                                  \
            _Pragma("unroll")                                                  \
            for (int ma = 0; ma < 2; ma++)                                     \
                _Pragma("unroll")                                              \
                for (int j = 0; j < 3; j++) {                                  \
                    MMA_BF16(acc[ma][j], ah[ma], bh[j][0], bh[j][1]);          \
                    MMA_BF16(acc[ma][j], ah[ma], bl[j][0], bl[j][1]);          \
                    MMA_BF16(acc[ma][j], al[ma], bh[j][0], bh[j][1]);          \
                }                                                              \
        }                                                                      \
    } while (0)

    CP_STAGE(0, 0);
    asm volatile("cp.async.wait_group 0;" ::: "memory");
    __syncthreads();

#pragma unroll 1
    for (int kt = 0; kt < NKT; kt++) {
        if (kt < NKT - 1) CP_STAGE((kt + 1) & 1, kt + 1);
        COMPUTE(kt & 1);
        asm volatile("cp.async.wait_group 0;" ::: "memory");
        __syncthreads();
    }

    // ---- Fused epilogue: stage acc -> smem, then masked cumsum -> g_prefix
    float* stage = (float*)smem;   // [128][SPITCH]
#pragma unroll
    for (int j = 0; j < 3; j++) {
        const int col = wn * 24 + j * 8 + qid * 2;
#pragma unroll
        for (int ma = 0; ma < 2; ma++) {
            const int r0 = wm * 32 + ma * 16 + grp;
            stage[r0 * SPITCH + col]           = acc[ma][j][0];
            stage[r0 * SPITCH + col + 1]       = acc[ma][j][1];
            stage[(r0 + 8) * SPITCH + col]     = acc[ma][j][2];
            stage[(r0 + 8) * SPITCH + col + 1] = acc[ma][j][3];
        }
    }
    __syncthreads();

    if (tid < 96) {
        const int bb = tid / 48;
        const int col = tid % 48;
        const int batch = (m0 >> 6) + bb;
        const int len = lengths[batch];
        const int gcol = n0 + col;
        const float bias = bo[gcol];
        float accu = 0.0f;
        float* gp = g_prefix + (size_t)(batch * NP1) * NOUT + gcol;
        gp[0] = 0.0f;
#pragma unroll 4
        for (int n = 0; n < Nn; n++) {
            const float v = stage[(bb * Nn + n) * SPITCH + col] + bias;
            if (n < len) accu += v;
            gp[(size_t)(n + 1) * NOUT] = accu;
        }
    }
}

// ---------------------------------------------------------------------------
// Kernel 3: span features + L2 norm, smem-tiled over 8x8 (l, r) tiles.
// Streaming (.cs) output stores; 5 blocks/SM via launch bounds.
// ---------------------------------------------------------------------------
#define STH 256

#define STG_CS4(ptr, v)                                                       \
    asm volatile("st.global.cs.v4.f32 [%0], {%1,%2,%3,%4};"                   \
                 :: "l"(ptr), "f"((v).x), "f"((v).y), "f"((v).z), "f"((v).w)  \
                 : "memory")

__global__ __launch_bounds__(STH, 5) void span_kernel(float* __restrict__ out)
{
    __shared__ float sL[8][NOUT];
    __shared__ float sR[8][NOUT];

    const int b = blockIdx.y;
    const int t = blockIdx.x;                 // 0..35, t = rt*(rt+1)/2 + lt
    int rt = 0;
    while ((rt + 1) * (rt + 2) / 2 <= t) rt++;
    const int lt = t - rt * (rt + 1) / 2;

    const int tid = threadIdx.x;
    const float* pb = g_prefix + (size_t)b * NP1 * NOUT;

    for (int i4 = tid; i4 < 16 * (NOUT / 4); i4 += STH) {
        const int row = i4 / (NOUT / 4);
        const int pos = i4 % (NOUT / 4);
        const int grow = (row < 8) ? (lt * 8 + row) : (rt * 8 + (row - 8) + 1);
        const float4 v = *(const float4*)(pb + (size_t)grow * NOUT + pos * 4);
        if (row < 8) *(float4*)&sL[row][pos * 4] = v;
        else         *(float4*)&sR[row - 8][pos * 4] = v;
    }
    __syncthreads();

    const int slot = tid / 60;        // 0..3 active, 4 = spare
    const int lane = tid % 60;
    const int base = (slot < 4) ? slot : 0;
    const bool diag = (lt == rt);

#pragma unroll 4
    for (int i = 0; i < 16; i++) {
        const int sp = base + 4 * i;          // 0..63
        const int li = sp & 7;
        const int ri = sp >> 3;

        const float4* Rp = (const float4*)&sR[ri][0];
        const float4* Lp = (const float4*)&sL[li][0];
        const float4 ra = Rp[lane],      la = Lp[lane];
        const float4 rb = Rp[60 + lane], lb = Lp[60 + lane];

        float4 da, db;
        da.x = ra.x - la.x; da.y = ra.y - la.y; da.z = ra.z - la.z; da.w = ra.w - la.w;
        db.x = rb.x - lb.x; db.y = rb.y - lb.y; db.z = rb.z - lb.z; db.w = rb.w - lb.w;

        float sqA = da.x * da.x;
        sqA = fmaf(da.y, da.y, sqA); sqA = fmaf(da.z, da.z, sqA); sqA = fmaf(da.w, da.w, sqA);
        float sqB = db.x * db.x;
        sqB = fmaf(db.y, db.y, sqB); sqB = fmaf(db.z, db.z, sqB); sqB = fmaf(db.w, db.w, sqB);

        sqA += __shfl_xor_sync(0xffffffffu, sqA, 1);
        sqA += __shfl_xor_sync(0xffffffffu, sqA, 2);
        sqB += __shfl_xor_sync(0xffffffffu, sqB, 1);
        sqB += __shfl_xor_sync(0xffffffffu, sqB, 2);

        const float invA = rsqrtf(sqA);
        const float invB = rsqrtf(sqB);

        if (slot < 4 && (!diag || li < ri)) {
            const int l = lt * 8 + li;
            const int r = rt * 8 + ri;
            const int k = r - l;
            const int s = (((k - 1) * (128 - k)) >> 1) + l;
            float* op = out + (size_t)(b * NSPAN + s) * NOUT;
            float4 oa, ob;
            oa.x = da.x * invA; oa.y = da.y * invA; oa.z = da.z * invA; oa.w = da.w * invA;
            ob.x = db.x * invB; ob.y = db.y * invB; ob.z = db.z * invB; ob.w = db.w * invB;
            STG_CS4(op + lane * 4, oa);
            STG_CS4(op + 240 + lane * 4, ob);
        }
    }
}

// ---------------------------------------------------------------------------
extern "C" void kernel_launch(void* const* d_in, const int* in_sizes, int n_in,
                              void* d_out, int out_size)
{
    const int*   x       = (const int*)d_in[0];
    const int*   lengths = (const int*)d_in[1];
    const float* emb     = (const float*)d_in[2];
    const float* w_out   = (const float*)d_in[3];
    const float* b_out   = (const float*)d_in[4];
    float* out = (float*)d_out;

    cudaFuncSetAttribute(gemm_kernel,
                         cudaFuncAttributeMaxDynamicSharedMemorySize, SMEM_DYN);

    prep_kernel<<<572, 256>>>(x, emb, w_out);
    gemm_kernel<<<dim3(ROWS / BM, NOUT / BN), 256, SMEM_DYN>>>(b_out, lengths);
    span_kernel<<<dim3(36, Bb), STH>>>(out);
}